// round 15
// baseline (speedup 1.0000x reference)
#include <cuda_runtime.h>
#include <cuda_fp16.h>
#include <cstdint>

#define S_LEN   4096
#define BATCH   4
#define D_MODEL 512
#define DHEAD   64
#define BSROWS  (BATCH * S_LEN)

// Scratch (allocation-free rule: __device__ globals) — all fp16
__device__ __half g_qh[BSROWS * DHEAD];
__device__ __half g_kh[BSROWS * DHEAD];
__device__ __half g_vt[BATCH * DHEAD * S_LEN];   // V TRANSPOSED [b][dv][seq]
__device__ __half g_attnh[BSROWS * DHEAD];
__device__ __half g_wqt[DHEAD * D_MODEL];   // transposed [n=64][k=512]
__device__ __half g_wkt[DHEAD * D_MODEL];
__device__ __half g_wvt[DHEAD * D_MODEL];
__device__ __half g_wot[D_MODEL * DHEAD];   // transposed [n=512][k=64]

__device__ __forceinline__ float ex2f(float x) {
    float y; asm("ex2.approx.f32 %0, %1;" : "=f"(y) : "f"(x)); return y;
}
__device__ __forceinline__ uint32_t h2pack(float lo, float hi) {
    __half2 h = __floats2half2_rn(lo, hi);
    return *reinterpret_cast<uint32_t*>(&h);
}
__device__ __forceinline__ float2 h2unpack(uint32_t u) {
    __half2 h = *reinterpret_cast<__half2*>(&u);
    return __half22float2(h);
}
__device__ __forceinline__ uint32_t smem_u32(const void* p) {
    uint32_t a;
    asm("{ .reg .u64 t; cvta.to.shared.u64 t, %1; cvt.u32.u64 %0, t; }" : "=r"(a) : "l"(p));
    return a;
}
__device__ __forceinline__ void cp16(uint32_t s, const void* g) {
    asm volatile("cp.async.cg.shared.global [%0], [%1], 16;" :: "r"(s), "l"(g));
}
__device__ __forceinline__ void mma16(float* d, const uint32_t* a, const uint32_t* b) {
    asm volatile(
        "mma.sync.aligned.m16n8k16.row.col.f32.f16.f16.f32 "
        "{%0,%1,%2,%3}, {%4,%5,%6,%7}, {%8,%9}, {%0,%1,%2,%3};"
        : "+f"(d[0]), "+f"(d[1]), "+f"(d[2]), "+f"(d[3])
        : "r"(a[0]), "r"(a[1]), "r"(a[2]), "r"(a[3]), "r"(b[0]), "r"(b[1]));
}
__device__ __forceinline__ void ldsm4(uint32_t& r0, uint32_t& r1, uint32_t& r2,
                                      uint32_t& r3, uint32_t addr) {
    asm volatile("ldmatrix.sync.aligned.m8n8.x4.shared.b16 {%0,%1,%2,%3}, [%4];"
        : "=r"(r0), "=r"(r1), "=r"(r2), "=r"(r3) : "r"(addr));
}

// ---------------------------------------------------------------------------
// Kernel 0: weights only -> fp16 TRANSPOSED ([n][k]).
// ---------------------------------------------------------------------------
#define NWEL  (D_MODEL * DHEAD)

__global__ void __launch_bounds__(256) preround_kernel(
    const float* __restrict__ Wq, const float* __restrict__ Wk,
    const float* __restrict__ Wv, const float* __restrict__ Wo)
{
    const int total = 4 * NWEL;
    for (int r = blockIdx.x * blockDim.x + threadIdx.x; r < total;
         r += gridDim.x * blockDim.x) {
        int seg = r >> 15, o = r & (NWEL - 1);
        if (seg < 3) {
            const float* W = (seg == 0) ? Wq : (seg == 1) ? Wk : Wv;
            __half* wt = (seg == 0) ? g_wqt : (seg == 1) ? g_wkt : g_wvt;
            int k = o >> 6, n = o & 63;
            wt[n * D_MODEL + k] = __float2half_rn(W[o]);
        } else {
            int k = o >> 9, n = o & 511;
            g_wot[n * DHEAD + k] = __float2half_rn(Wo[o]);
        }
    }
}

// ---------------------------------------------------------------------------
// Kernel 1: MERGED fp16 QKV projection, fp32 X read directly (unchanged).
// ---------------------------------------------------------------------------
#define XB0 0
#define XB1 10240
#define WBASE 20480
#define WBUF_STRIDE 15360
#define WMODE_STRIDE 5120
#define QKV_SMEM 51200

__global__ void __launch_bounds__(256) qkv_tc_kernel(
    const float* __restrict__ x,
    const float* __restrict__ bq, const float* __restrict__ bk,
    const float* __restrict__ bv)
{
    extern __shared__ char smc[];
    __half* hs = (__half*)smc;

    const int tid = threadIdx.x;
    const int w = tid >> 5, lane = tid & 31, g = lane >> 2, t4 = lane & 3;
    const int wm = w & 3, wn = w >> 2;
    const int rowBase = blockIdx.x * 128;
    const uint32_t smb = smem_u32(smc);

    const int xr = tid >> 1, xc2 = tid & 1;
    const int wr = tid >> 2, wc2 = tid & 3;

    const float* xrow = x + (size_t)(rowBase + xr) * D_MODEL + xc2 * 16;

    float4 xv[4];
    #pragma unroll
    for (int i = 0; i < 4; i++) xv[i] = *(const float4*)(xrow + 4 * i);

    {
        const size_t woff = (size_t)wr * D_MODEL + wc2 * 8;
        uint32_t wa = smb + WBASE + wr * 80 + wc2 * 16;
        cp16(wa,                    g_wqt + woff);
        cp16(wa + WMODE_STRIDE,     g_wkt + woff);
        cp16(wa + 2 * WMODE_STRIDE, g_wvt + woff);
        asm volatile("cp.async.commit_group;" ::: "memory");
    }

    float accQ[2][4][4] = {}, accK[2][4][4] = {}, accV[2][4][4] = {};

    for (int kc = 0; kc < 16; kc++) {
        __syncthreads();

        {
            uint4 u0, u1;
            u0.x = h2pack(xv[0].x, xv[0].y); u0.y = h2pack(xv[0].z, xv[0].w);
            u0.z = h2pack(xv[1].x, xv[1].y); u0.w = h2pack(xv[1].z, xv[1].w);
            u1.x = h2pack(xv[2].x, xv[2].y); u1.y = h2pack(xv[2].z, xv[2].w);
            u1.z = h2pack(xv[3].x, xv[3].y); u1.w = h2pack(xv[3].z, xv[3].w);
            char* xb = smc + ((kc & 1) ? XB1 : XB0) + xr * 80 + xc2 * 32;
            *(uint4*)xb = u0;
            *(uint4*)(xb + 16) = u1;
        }

        if (kc < 15) {
            const float* xp = xrow + (kc + 1) * 32;
            #pragma unroll
            for (int i = 0; i < 4; i++) xv[i] = *(const float4*)(xp + 4 * i);
            const size_t woff = (size_t)wr * D_MODEL + (kc + 1) * 32 + wc2 * 8;
            uint32_t wa = smb + WBASE + ((kc + 1) & 1) * WBUF_STRIDE + wr * 80 + wc2 * 16;
            cp16(wa,                    g_wqt + woff);
            cp16(wa + WMODE_STRIDE,     g_wkt + woff);
            cp16(wa + 2 * WMODE_STRIDE, g_wvt + woff);
            asm volatile("cp.async.commit_group;" ::: "memory");
            asm volatile("cp.async.wait_group 1;" ::: "memory");
        } else {
            asm volatile("cp.async.wait_group 0;" ::: "memory");
        }
        __syncthreads();

        const __half* Xb = hs + ((kc & 1) ? XB1 : XB0) / 2;
        const __half* Wq2 = hs + (WBASE + (kc & 1) * WBUF_STRIDE) / 2;
        const __half* Wk2 = Wq2 + WMODE_STRIDE / 2;
        const __half* Wv2 = Wk2 + WMODE_STRIDE / 2;

        #pragma unroll
        for (int ks = 0; ks < 2; ks++) {
            const int k0 = 16 * ks;
            uint32_t af[2][4];
            #pragma unroll
            for (int i = 0; i < 2; i++) {
                const int m0 = 32 * wm + 16 * i;
                af[i][0] = *(const uint32_t*)&Xb[(m0 + g) * 40 + k0 + 2 * t4];
                af[i][1] = *(const uint32_t*)&Xb[(m0 + g + 8) * 40 + k0 + 2 * t4];
                af[i][2] = *(const uint32_t*)&Xb[(m0 + g) * 40 + k0 + 8 + 2 * t4];
                af[i][3] = *(const uint32_t*)&Xb[(m0 + g + 8) * 40 + k0 + 8 + 2 * t4];
            }
            #pragma unroll
            for (int nt = 0; nt < 4; nt++) {
                const int n0 = 32 * wn + 8 * nt;
                uint32_t bf[2];
                bf[0] = *(const uint32_t*)&Wq2[(n0 + g) * 40 + k0 + 2 * t4];
                bf[1] = *(const uint32_t*)&Wq2[(n0 + g) * 40 + k0 + 8 + 2 * t4];
                mma16(accQ[0][nt], af[0], bf);
                mma16(accQ[1][nt], af[1], bf);
                bf[0] = *(const uint32_t*)&Wk2[(n0 + g) * 40 + k0 + 2 * t4];
                bf[1] = *(const uint32_t*)&Wk2[(n0 + g) * 40 + k0 + 8 + 2 * t4];
                mma16(accK[0][nt], af[0], bf);
                mma16(accK[1][nt], af[1], bf);
                bf[0] = *(const uint32_t*)&Wv2[(n0 + g) * 40 + k0 + 2 * t4];
                bf[1] = *(const uint32_t*)&Wv2[(n0 + g) * 40 + k0 + 8 + 2 * t4];
                mma16(accV[0][nt], af[0], bf);
                mma16(accV[1][nt], af[1], bf);
            }
        }
    }

    #pragma unroll
    for (int i = 0; i < 2; i++) {
        #pragma unroll
        for (int nt = 0; nt < 4; nt++) {
            const int col = 32 * wn + 8 * nt + 2 * t4;
            const int rA = rowBase + 32 * wm + 16 * i + g;
            {
                const float b0 = bq[col], b1 = bq[col + 1];
                *(uint32_t*)&g_qh[(size_t)rA * DHEAD + col] =
                    h2pack(accQ[i][nt][0] + b0, accQ[i][nt][1] + b1);
                *(uint32_t*)&g_qh[(size_t)(rA + 8) * DHEAD + col] =
                    h2pack(accQ[i][nt][2] + b0, accQ[i][nt][3] + b1);
            }
            {
                const float b0 = bk[col], b1 = bk[col + 1];
                *(uint32_t*)&g_kh[(size_t)rA * DHEAD + col] =
                    h2pack(accK[i][nt][0] + b0, accK[i][nt][1] + b1);
                *(uint32_t*)&g_kh[(size_t)(rA + 8) * DHEAD + col] =
                    h2pack(accK[i][nt][2] + b0, accK[i][nt][3] + b1);
            }
            {
                const float b0 = bv[col], b1 = bv[col + 1];
                const int bb = rA >> 12, s0 = rA & (S_LEN - 1);
                __half* vt = g_vt + (size_t)bb * DHEAD * S_LEN;
                vt[(size_t)col * S_LEN + s0]           = __float2half_rn(accV[i][nt][0] + b0);
                vt[(size_t)(col + 1) * S_LEN + s0]     = __float2half_rn(accV[i][nt][1] + b1);
                vt[(size_t)col * S_LEN + s0 + 8]       = __float2half_rn(accV[i][nt][2] + b0);
                vt[(size_t)(col + 1) * S_LEN + s0 + 8] = __float2half_rn(accV[i][nt][3] + b1);
            }
        }
    }
}

// attention smem (bytes): Q | 3x (K,V) tile pairs | RED fp32 (aliases bufs)
#define QB   0
#define K0B  9216
#define V0B  18432
#define K1B  27648
#define V1B  36864
#define K2B  46080
#define V2B  55296
#define REDB 9216
#define LB   78848
#define ATTN_SMEM 79872

// ---------------------------------------------------------------------------
// Kernel 2: fp16 causal flash attention — TRIPLE-buffered K/V, ONE barrier
// per iteration (tile kb+2 issued right after iter-kb barrier: its buffer
// was last read in iter kb-1, which happens-before this barrier).
// ---------------------------------------------------------------------------
__global__ void __launch_bounds__(512, 1) attn_mma_kernel()
{
    extern __shared__ char smc[];
    __half* hs = (__half*)smc;
    float* fRED = (float*)(smc + REDB);
    float* fL   = (float*)(smc + LB);

    const int tid  = threadIdx.x;
    const int w    = tid >> 5, lane = tid & 31;
    const int g    = lane >> 2, t4 = lane & 3;
    const int b    = blockIdx.y;
    const int wm   = w & 3, wk = w >> 2;
    const int qr0  = 16 * wm;
    const int nc0  = 16 * wk;
    const uint32_t smb = smem_u32(smc);

    const __half* kg = g_kh + (size_t)b * S_LEN * DHEAD;
    const __half* vt = g_vt + (size_t)b * DHEAD * S_LEN;
    const float SCL2 = 0.18033688011112042f;

    const int lrow = tid >> 3, lch = tid & 7;

    const int KB_[3] = { K0B, K1B, K2B };
    const int VB_[3] = { V0B, V1B, V2B };

    const uint32_t kAddrOff = (uint32_t)(((nc0 + (lane & 7)) * 72 + ((lane >> 3) * 8)) * 2);
    const uint32_t vAddrOff = (uint32_t)(((8 * (lane >> 4) + (lane & 7)) * 72
                                          + nc0 + 8 * ((lane >> 3) & 1)) * 2);

    int jlist[2] = { (int)blockIdx.x, 63 - (int)blockIdx.x };

    #pragma unroll 1
    for (int pb = 0; pb < 2; pb++) {
        const int j = jlist[pb];
        const size_t qrow = (size_t)b * S_LEN + 64 * j;

        // preload Q + tiles 0 and (if any) 1
        {
            const __half* qp = g_qh + (qrow + lrow) * DHEAD + lch * 8;
            cp16(smb + QB + lrow * 144 + lch * 16, qp);
            const __half* kp = kg + (size_t)lrow * DHEAD + lch * 8;
            cp16(smb + K0B + lrow * 144 + lch * 16, kp);
            const __half* vp = vt + (size_t)lrow * S_LEN + lch * 8;
            cp16(smb + V0B + lrow * 144 + lch * 16, vp);
            asm volatile("cp.async.commit_group;" ::: "memory");
        }
        if (j >= 1) {
            const __half* kp = kg + ((size_t)64 + lrow) * DHEAD + lch * 8;
            cp16(smb + K1B + lrow * 144 + lch * 16, kp);
            const __half* vp = vt + (size_t)lrow * S_LEN + 64 + lch * 8;
            cp16(smb + V1B + lrow * 144 + lch * 16, vp);
            asm volatile("cp.async.commit_group;" ::: "memory");
            asm volatile("cp.async.wait_group 1;" ::: "memory");
        } else {
            asm volatile("cp.async.wait_group 0;" ::: "memory");
        }
        __syncthreads();

        uint32_t qf[4][4];
        #pragma unroll
        for (int s = 0; s < 4; s++) {
            const int k0 = 16 * s;
            qf[s][0] = *(const uint32_t*)&hs[(qr0 + g) * 72 + k0 + 2 * t4];
            qf[s][1] = *(const uint32_t*)&hs[(qr0 + g + 8) * 72 + k0 + 2 * t4];
            qf[s][2] = *(const uint32_t*)&hs[(qr0 + g) * 72 + k0 + 8 + 2 * t4];
            qf[s][3] = *(const uint32_t*)&hs[(qr0 + g + 8) * 72 + k0 + 8 + 2 * t4];
        }

        float oacc[8][4] = {};
        float l0 = 0.f, l1 = 0.f;
        int bufc = 0;

        for (int kb = 0; kb <= j; kb++) {
            if (kb > 0) {   // ensure tile kb arrived; single barrier per iter
                if (kb < j) { asm volatile("cp.async.wait_group 1;" ::: "memory"); }
                else        { asm volatile("cp.async.wait_group 0;" ::: "memory"); }
                __syncthreads();
            }
            if (kb + 2 <= j) {   // issue tile kb+2 into the just-freed buffer
                int nb = bufc + 2; if (nb >= 3) nb -= 3;
                const __half* kp = kg + ((size_t)(kb + 2) * 64 + lrow) * DHEAD + lch * 8;
                cp16(smb + KB_[nb] + lrow * 144 + lch * 16, kp);
                const __half* vp = vt + (size_t)lrow * S_LEN + (kb + 2) * 64 + lch * 8;
                cp16(smb + VB_[nb] + lrow * 144 + lch * 16, vp);
                asm volatile("cp.async.commit_group;" ::: "memory");
            }

            const int kOffB = KB_[bufc];
            const int vOffB = VB_[bufc];

            // --- K fragments via ldmatrix.x4 ---
            uint32_t kf[2][8];
            {
                const uint32_t kb0 = smb + kOffB + kAddrOff;
                ldsm4(kf[0][0], kf[0][1], kf[0][2], kf[0][3], kb0);
                ldsm4(kf[0][4], kf[0][5], kf[0][6], kf[0][7], kb0 + 64);
                const uint32_t kb1 = kb0 + 8 * 144;
                ldsm4(kf[1][0], kf[1][1], kf[1][2], kf[1][3], kb1);
                ldsm4(kf[1][4], kf[1][5], kf[1][6], kf[1][7], kb1 + 64);
            }

            // --- S = Q K^T ---
            float sacc[2][4] = {};
            #pragma unroll
            for (int s = 0; s < 4; s++) {
                #pragma unroll
                for (int c = 0; c < 2; c++)
                    mma16(sacc[c], qf[s], &kf[c][2 * s]);
            }

            // --- softmax (no-rescale) -> fp16 P packed as A-frag ---
            const bool dg = (kb == j);
            const int ra = qr0 + g, rb = ra + 8;
            uint32_t pa[4];
            #pragma unroll
            for (int c = 0; c < 2; c++) {
                const int cb = nc0 + 8 * c + 2 * t4;
                float p00 = (!dg || cb     <= ra) ? ex2f(sacc[c][0] * SCL2) : 0.f;
                float p01 = (!dg || cb + 1 <= ra) ? ex2f(sacc[c][1] * SCL2) : 0.f;
                float p10 = (!dg || cb     <= rb) ? ex2f(sacc[c][2] * SCL2) : 0.f;
                float p11 = (!dg || cb + 1 <= rb) ? ex2f(sacc[c][3] * SCL2) : 0.f;
                pa[2 * c]     = h2pack(p00, p01);
                pa[2 * c + 1] = h2pack(p10, p11);
                float2 fa = h2unpack(pa[2 * c]);
                float2 fb = h2unpack(pa[2 * c + 1]);
                l0 += fa.x + fa.y;
                l1 += fb.x + fb.y;
            }

            // --- V fragments via ldmatrix.x4, then PV ---
            uint32_t vf[16];
            {
                const uint32_t vb0 = smb + vOffB + vAddrOff;
                ldsm4(vf[0],  vf[1],  vf[2],  vf[3],  vb0);
                ldsm4(vf[4],  vf[5],  vf[6],  vf[7],  vb0 + 16 * 144);
                ldsm4(vf[8],  vf[9],  vf[10], vf[11], vb0 + 32 * 144);
                ldsm4(vf[12], vf[13], vf[14], vf[15], vb0 + 48 * 144);
            }
            #pragma unroll
            for (int nt = 0; nt < 8; nt++)
                mma16(oacc[nt], pa, &vf[2 * nt]);

            bufc = (bufc + 1 == 3) ? 0 : bufc + 1;
        }

        l0 += __shfl_xor_sync(0xffffffffu, l0, 1);
        l0 += __shfl_xor_sync(0xffffffffu, l0, 2);
        l1 += __shfl_xor_sync(0xffffffffu, l1, 1);
        l1 += __shfl_xor_sync(0xffffffffu, l1, 2);

        __syncthreads();   // all K/V reads done; RED may alias the buffers

        if (t4 == 0) {
            fL[w * 16 + g]     = l0;
            fL[w * 16 + g + 8] = l1;
        }
        {
            float* rw = fRED + w * (16 * 68);
            #pragma unroll
            for (int nt = 0; nt < 8; nt++) {
                const int cb = 8 * nt + 2 * t4;
                *(float2*)&rw[g * 68 + cb]       = make_float2(oacc[nt][0], oacc[nt][1]);
                *(float2*)&rw[(g + 8) * 68 + cb] = make_float2(oacc[nt][2], oacc[nt][3]);
            }
        }
        __syncthreads();

        {
            const int r  = tid >> 3;
            const int c0 = (tid & 7) * 8;
            const int wmr = r >> 4, ri = r & 15;
            float lt = 0.f;
            #pragma unroll
            for (int k = 0; k < 4; k++)
                lt += fL[(wmr + 4 * k) * 16 + ri];
            const float inv = 1.f / lt;

            float acc8[8] = {};
            #pragma unroll
            for (int k = 0; k < 4; k++) {
                const float* rp = fRED + (wmr + 4 * k) * (16 * 68) + ri * 68 + c0;
                #pragma unroll
                for (int e = 0; e < 8; e++) acc8[e] += rp[e];
            }
            __half* op = g_attnh + (qrow + r) * DHEAD + c0;
            #pragma unroll
            for (int e = 0; e < 8; e += 2)
                *(uint32_t*)&op[e] = h2pack(acc8[e] * inv, acc8[e + 1] * inv);
        }
        __syncthreads();   // RED/L reads done before next pair member reloads
    }
}

// ---------------------------------------------------------------------------
// Kernel 3: fp16 output projection, 2 row-tiles/CTA. grid = (64, 4), 256 thr.
// ---------------------------------------------------------------------------
#define PA0_B 0
#define PA1_B 18432
#define PB_B  36864
#define PROJ_SMEM 55296

__global__ void __launch_bounds__(256) proj_tc_kernel(
    const float* __restrict__ bo, float* __restrict__ out)
{
    extern __shared__ char smc[];
    __half* hs = (__half*)smc;
    const int tid = threadIdx.x;
    const int w = tid >> 5, lane = tid & 31, g = lane >> 2, t4 = lane & 3;
    const int wm = w & 3, wn = w >> 2;
    const int rowBase0 = blockIdx.x * 256;      // 2 tiles of 128 rows
    const int nBase    = blockIdx.y * 128;
    const uint32_t smb = smem_u32(smc);

    const int r = tid >> 1, h64 = tid & 1;

    {
        const __half* bp = g_wot + (size_t)(nBase + r) * DHEAD + h64 * 32;
        uint32_t ba = smb + PB_B + r * 144 + h64 * 64;
        #pragma unroll
        for (int i = 0; i < 4; i++) cp16(ba + 16 * i, bp + 8 * i);
        const __half* ap = g_attnh + (size_t)(rowBase0 + r) * DHEAD + h64 * 32;
        uint32_t aa = smb + PA0_B + r * 144 + h64 * 64;
        #pragma unroll
        for (int i = 0; i < 4; i++) cp16(aa + 16 * i, ap + 8 * i);
        asm volatile("cp.async.commit_group;" ::: "memory");
    }

    const __half* Bh = hs + PB_B / 2;

    #pragma unroll 1
    for (int t = 0; t < 2; t++) {
        __syncthreads();
        if (t < 1) {
            const __half* ap = g_attnh + (size_t)(rowBase0 + 128 + r) * DHEAD + h64 * 32;
            uint32_t aa = smb + PA1_B + r * 144 + h64 * 64;
            #pragma unroll
            for (int i = 0; i < 4; i++) cp16(aa + 16 * i, ap + 8 * i);
            asm volatile("cp.async.commit_group;" ::: "memory");
            asm volatile("cp.async.wait_group 1;" ::: "memory");
        } else {
            asm volatile("cp.async.wait_group 0;" ::: "memory");
        }
        __syncthreads();

        const __half* Ah = hs + ((t & 1) ? PA1_B : PA0_B) / 2;
        const int rowBase = rowBase0 + t * 128;

        float acc[2][8][4] = {};
        #pragma unroll
        for (int s = 0; s < 4; s++) {
            const int k0 = 16 * s;
            uint32_t af[2][4];
            #pragma unroll
            for (int i = 0; i < 2; i++) {
                const int m0 = 32 * wm + 16 * i;
                af[i][0] = *(const uint32_t*)&Ah[(m0 + g) * 72 + k0 + 2 * t4];
                af[i][1] = *(const uint32_t*)&Ah[(m0 + g + 8) * 72 + k0 + 2 * t4];
                af[i][2] = *(const uint32_t*)&Ah[(m0 + g) * 72 + k0 + 8 + 2 * t4];
                af[i][3] = *(const uint32_t*)&Ah[(m0 + g + 8) * 72 + k0 + 8 + 2 * t4];
            }
            #pragma unroll
            for (int nt = 0; nt < 8; nt++) {
                const int n0 = 64 * wn + 8 * nt;
                uint32_t bf[2];
                bf[0] = *(const uint32_t*)&Bh[(n0 + g) * 72 + k0 + 2 * t4];
                bf[1] = *(const uint32_t*)&Bh[(n0 + g) * 72 + k0 + 8 + 2 * t4];
                mma16(acc[0][nt], af[0], bf);
                mma16(acc[1][nt], af[1], bf);
            }
        }

        #pragma unroll
        for (int i = 0; i < 2; i++) {
            #pragma unroll
            for (int nt = 0; nt < 8; nt++) {
                const int col = nBase + 64 * wn + 8 * nt + 2 * t4;
                const float b0 = bo[col], b1 = bo[col + 1];
                const int rA = rowBase + 32 * wm + 16 * i + g;
                *(float2*)&out[(size_t)rA * D_MODEL + col] =
                    make_float2(acc[i][nt][0] + b0, acc[i][nt][1] + b1);
                *(float2*)&out[(size_t)(rA + 8) * D_MODEL + col] =
                    make_float2(acc[i][nt][2] + b0, acc[i][nt][3] + b1);
            }
        }
    }
}

// ---------------------------------------------------------------------------
extern "C" void kernel_launch(void* const* d_in, const int* in_sizes, int n_in,
                              void* d_out, int out_size)
{
    const float* x  = (const float*)d_in[0];
    const float* Wq = (const float*)d_in[1];
    const float* bq = (const float*)d_in[2];
    const float* Wk = (const float*)d_in[3];
    const float* bk = (const float*)d_in[4];
    const float* Wv = (const float*)d_in[5];
    const float* bv = (const float*)d_in[6];
    const float* Wo = (const float*)d_in[7];
    const float* bo = (const float*)d_in[8];
    float* out = (float*)d_out;

    cudaFuncSetAttribute(qkv_tc_kernel,
                         cudaFuncAttributeMaxDynamicSharedMemorySize, QKV_SMEM);
    cudaFuncSetAttribute(attn_mma_kernel,
                         cudaFuncAttributeMaxDynamicSharedMemorySize, ATTN_SMEM);
    cudaFuncSetAttribute(proj_tc_kernel,
                         cudaFuncAttributeMaxDynamicSharedMemorySize, PROJ_SMEM);

    preround_kernel<<<128, 256>>>(Wq, Wk, Wv, Wo);
    qkv_tc_kernel<<<BSROWS / 128, 256, QKV_SMEM>>>(x, bq, bk, bv);
    attn_mma_kernel<<<dim3(32, BATCH), 512, ATTN_SMEM>>>();
    proj_tc_kernel<<<dim3(64, D_MODEL / 128), 256, PROJ_SMEM>>>(bo, out);
}

// round 16
// speedup vs baseline: 1.0392x; 1.0392x over previous
#include <cuda_runtime.h>
#include <cuda_fp16.h>
#include <cstdint>

#define S_LEN   4096
#define BATCH   4
#define D_MODEL 512
#define DHEAD   64
#define BSROWS  (BATCH * S_LEN)

// Scratch (allocation-free rule: __device__ globals) — all fp16
__device__ __half g_qh[BSROWS * DHEAD];
__device__ __half g_kh[BSROWS * DHEAD];
__device__ __half g_vt[BATCH * DHEAD * S_LEN];   // V TRANSPOSED [b][dv][seq]
__device__ __half g_attnh[BSROWS * DHEAD];
__device__ __half g_wqt[DHEAD * D_MODEL];   // transposed [n=64][k=512]
__device__ __half g_wkt[DHEAD * D_MODEL];
__device__ __half g_wvt[DHEAD * D_MODEL];
__device__ __half g_wot[D_MODEL * DHEAD];   // transposed [n=512][k=64]

__device__ __forceinline__ float ex2f(float x) {
    float y; asm("ex2.approx.f32 %0, %1;" : "=f"(y) : "f"(x)); return y;
}
__device__ __forceinline__ uint32_t h2pack(float lo, float hi) {
    __half2 h = __floats2half2_rn(lo, hi);
    return *reinterpret_cast<uint32_t*>(&h);
}
__device__ __forceinline__ float2 h2unpack(uint32_t u) {
    __half2 h = *reinterpret_cast<__half2*>(&u);
    return __half22float2(h);
}
__device__ __forceinline__ uint32_t smem_u32(const void* p) {
    uint32_t a;
    asm("{ .reg .u64 t; cvta.to.shared.u64 t, %1; cvt.u32.u64 %0, t; }" : "=r"(a) : "l"(p));
    return a;
}
__device__ __forceinline__ void cp16(uint32_t s, const void* g) {
    asm volatile("cp.async.cg.shared.global [%0], [%1], 16;" :: "r"(s), "l"(g));
}
__device__ __forceinline__ void mma16(float* d, const uint32_t* a, const uint32_t* b) {
    asm volatile(
        "mma.sync.aligned.m16n8k16.row.col.f32.f16.f16.f32 "
        "{%0,%1,%2,%3}, {%4,%5,%6,%7}, {%8,%9}, {%0,%1,%2,%3};"
        : "+f"(d[0]), "+f"(d[1]), "+f"(d[2]), "+f"(d[3])
        : "r"(a[0]), "r"(a[1]), "r"(a[2]), "r"(a[3]), "r"(b[0]), "r"(b[1]));
}
__device__ __forceinline__ void ldsm4(uint32_t& r0, uint32_t& r1, uint32_t& r2,
                                      uint32_t& r3, uint32_t addr) {
    asm volatile("ldmatrix.sync.aligned.m8n8.x4.shared.b16 {%0,%1,%2,%3}, [%4];"
        : "=r"(r0), "=r"(r1), "=r"(r2), "=r"(r3) : "r"(addr));
}

// ---------------------------------------------------------------------------
// Kernel 0: weights only -> fp16 TRANSPOSED ([n][k]).
// ---------------------------------------------------------------------------
#define NWEL  (D_MODEL * DHEAD)

__global__ void __launch_bounds__(256) preround_kernel(
    const float* __restrict__ Wq, const float* __restrict__ Wk,
    const float* __restrict__ Wv, const float* __restrict__ Wo)
{
    const int total = 4 * NWEL;
    for (int r = blockIdx.x * blockDim.x + threadIdx.x; r < total;
         r += gridDim.x * blockDim.x) {
        int seg = r >> 15, o = r & (NWEL - 1);
        if (seg < 3) {
            const float* W = (seg == 0) ? Wq : (seg == 1) ? Wk : Wv;
            __half* wt = (seg == 0) ? g_wqt : (seg == 1) ? g_wkt : g_wvt;
            int k = o >> 6, n = o & 63;
            wt[n * D_MODEL + k] = __float2half_rn(W[o]);
        } else {
            int k = o >> 9, n = o & 511;
            g_wot[n * DHEAD + k] = __float2half_rn(Wo[o]);
        }
    }
}

// ---------------------------------------------------------------------------
// Kernel 1: MERGED fp16 QKV projection, fp32 X read directly (unchanged R14).
// ---------------------------------------------------------------------------
#define XB0 0
#define XB1 10240
#define WBASE 20480
#define WBUF_STRIDE 15360
#define WMODE_STRIDE 5120
#define QKV_SMEM 51200

__global__ void __launch_bounds__(256) qkv_tc_kernel(
    const float* __restrict__ x,
    const float* __restrict__ bq, const float* __restrict__ bk,
    const float* __restrict__ bv)
{
    extern __shared__ char smc[];
    __half* hs = (__half*)smc;

    const int tid = threadIdx.x;
    const int w = tid >> 5, lane = tid & 31, g = lane >> 2, t4 = lane & 3;
    const int wm = w & 3, wn = w >> 2;
    const int rowBase = blockIdx.x * 128;
    const uint32_t smb = smem_u32(smc);

    const int xr = tid >> 1, xc2 = tid & 1;
    const int wr = tid >> 2, wc2 = tid & 3;

    const float* xrow = x + (size_t)(rowBase + xr) * D_MODEL + xc2 * 16;

    float4 xv[4];
    #pragma unroll
    for (int i = 0; i < 4; i++) xv[i] = *(const float4*)(xrow + 4 * i);

    {
        const size_t woff = (size_t)wr * D_MODEL + wc2 * 8;
        uint32_t wa = smb + WBASE + wr * 80 + wc2 * 16;
        cp16(wa,                    g_wqt + woff);
        cp16(wa + WMODE_STRIDE,     g_wkt + woff);
        cp16(wa + 2 * WMODE_STRIDE, g_wvt + woff);
        asm volatile("cp.async.commit_group;" ::: "memory");
    }

    float accQ[2][4][4] = {}, accK[2][4][4] = {}, accV[2][4][4] = {};

    for (int kc = 0; kc < 16; kc++) {
        __syncthreads();

        {
            uint4 u0, u1;
            u0.x = h2pack(xv[0].x, xv[0].y); u0.y = h2pack(xv[0].z, xv[0].w);
            u0.z = h2pack(xv[1].x, xv[1].y); u0.w = h2pack(xv[1].z, xv[1].w);
            u1.x = h2pack(xv[2].x, xv[2].y); u1.y = h2pack(xv[2].z, xv[2].w);
            u1.z = h2pack(xv[3].x, xv[3].y); u1.w = h2pack(xv[3].z, xv[3].w);
            char* xb = smc + ((kc & 1) ? XB1 : XB0) + xr * 80 + xc2 * 32;
            *(uint4*)xb = u0;
            *(uint4*)(xb + 16) = u1;
        }

        if (kc < 15) {
            const float* xp = xrow + (kc + 1) * 32;
            #pragma unroll
            for (int i = 0; i < 4; i++) xv[i] = *(const float4*)(xp + 4 * i);
            const size_t woff = (size_t)wr * D_MODEL + (kc + 1) * 32 + wc2 * 8;
            uint32_t wa = smb + WBASE + ((kc + 1) & 1) * WBUF_STRIDE + wr * 80 + wc2 * 16;
            cp16(wa,                    g_wqt + woff);
            cp16(wa + WMODE_STRIDE,     g_wkt + woff);
            cp16(wa + 2 * WMODE_STRIDE, g_wvt + woff);
            asm volatile("cp.async.commit_group;" ::: "memory");
            asm volatile("cp.async.wait_group 1;" ::: "memory");
        } else {
            asm volatile("cp.async.wait_group 0;" ::: "memory");
        }
        __syncthreads();

        const __half* Xb = hs + ((kc & 1) ? XB1 : XB0) / 2;
        const __half* Wq2 = hs + (WBASE + (kc & 1) * WBUF_STRIDE) / 2;
        const __half* Wk2 = Wq2 + WMODE_STRIDE / 2;
        const __half* Wv2 = Wk2 + WMODE_STRIDE / 2;

        #pragma unroll
        for (int ks = 0; ks < 2; ks++) {
            const int k0 = 16 * ks;
            uint32_t af[2][4];
            #pragma unroll
            for (int i = 0; i < 2; i++) {
                const int m0 = 32 * wm + 16 * i;
                af[i][0] = *(const uint32_t*)&Xb[(m0 + g) * 40 + k0 + 2 * t4];
                af[i][1] = *(const uint32_t*)&Xb[(m0 + g + 8) * 40 + k0 + 2 * t4];
                af[i][2] = *(const uint32_t*)&Xb[(m0 + g) * 40 + k0 + 8 + 2 * t4];
                af[i][3] = *(const uint32_t*)&Xb[(m0 + g + 8) * 40 + k0 + 8 + 2 * t4];
            }
            #pragma unroll
            for (int nt = 0; nt < 4; nt++) {
                const int n0 = 32 * wn + 8 * nt;
                uint32_t bf[2];
                bf[0] = *(const uint32_t*)&Wq2[(n0 + g) * 40 + k0 + 2 * t4];
                bf[1] = *(const uint32_t*)&Wq2[(n0 + g) * 40 + k0 + 8 + 2 * t4];
                mma16(accQ[0][nt], af[0], bf);
                mma16(accQ[1][nt], af[1], bf);
                bf[0] = *(const uint32_t*)&Wk2[(n0 + g) * 40 + k0 + 2 * t4];
                bf[1] = *(const uint32_t*)&Wk2[(n0 + g) * 40 + k0 + 8 + 2 * t4];
                mma16(accK[0][nt], af[0], bf);
                mma16(accK[1][nt], af[1], bf);
                bf[0] = *(const uint32_t*)&Wv2[(n0 + g) * 40 + k0 + 2 * t4];
                bf[1] = *(const uint32_t*)&Wv2[(n0 + g) * 40 + k0 + 8 + 2 * t4];
                mma16(accV[0][nt], af[0], bf);
                mma16(accV[1][nt], af[1], bf);
            }
        }
    }

    #pragma unroll
    for (int i = 0; i < 2; i++) {
        #pragma unroll
        for (int nt = 0; nt < 4; nt++) {
            const int col = 32 * wn + 8 * nt + 2 * t4;
            const int rA = rowBase + 32 * wm + 16 * i + g;
            {
                const float b0 = bq[col], b1 = bq[col + 1];
                *(uint32_t*)&g_qh[(size_t)rA * DHEAD + col] =
                    h2pack(accQ[i][nt][0] + b0, accQ[i][nt][1] + b1);
                *(uint32_t*)&g_qh[(size_t)(rA + 8) * DHEAD + col] =
                    h2pack(accQ[i][nt][2] + b0, accQ[i][nt][3] + b1);
            }
            {
                const float b0 = bk[col], b1 = bk[col + 1];
                *(uint32_t*)&g_kh[(size_t)rA * DHEAD + col] =
                    h2pack(accK[i][nt][0] + b0, accK[i][nt][1] + b1);
                *(uint32_t*)&g_kh[(size_t)(rA + 8) * DHEAD + col] =
                    h2pack(accK[i][nt][2] + b0, accK[i][nt][3] + b1);
            }
            {
                const float b0 = bv[col], b1 = bv[col + 1];
                const int bb = rA >> 12, s0 = rA & (S_LEN - 1);
                __half* vt = g_vt + (size_t)bb * DHEAD * S_LEN;
                vt[(size_t)col * S_LEN + s0]           = __float2half_rn(accV[i][nt][0] + b0);
                vt[(size_t)(col + 1) * S_LEN + s0]     = __float2half_rn(accV[i][nt][1] + b1);
                vt[(size_t)col * S_LEN + s0 + 8]       = __float2half_rn(accV[i][nt][2] + b0);
                vt[(size_t)(col + 1) * S_LEN + s0 + 8] = __float2half_rn(accV[i][nt][3] + b1);
            }
        }
    }
}

// attention smem (bytes): Q | K0 V0 K1 V1 (each 9216) | RED fp32 (aliases)
#define QB   0
#define K0B  9216
#define V0B  18432
#define K1B  27648
#define V1B  36864
#define REDB 9216
#define LB   78848
#define ATTN_SMEM 79872

// ---------------------------------------------------------------------------
// Kernel 2: fp16 causal flash attention — DOUBLE-buffered K/V with ONE
// barrier per iteration: wait(tile kb) -> barrier -> issue tile kb+1 into
// buffer (kb+1)&1 (last read in iter kb-1, safe past the barrier) -> compute.
// All addressing static (kb&1). Otherwise identical to the 90.8us R14 kernel.
// ---------------------------------------------------------------------------
__global__ void __launch_bounds__(512, 1) attn_mma_kernel()
{
    extern __shared__ char smc[];
    __half* hs = (__half*)smc;
    float* fRED = (float*)(smc + REDB);
    float* fL   = (float*)(smc + LB);

    const int tid  = threadIdx.x;
    const int w    = tid >> 5, lane = tid & 31;
    const int g    = lane >> 2, t4 = lane & 3;
    const int b    = blockIdx.y;
    const int wm   = w & 3, wk = w >> 2;
    const int qr0  = 16 * wm;
    const int nc0  = 16 * wk;
    const uint32_t smb = smem_u32(smc);

    const __half* kg = g_kh + (size_t)b * S_LEN * DHEAD;
    const __half* vt = g_vt + (size_t)b * DHEAD * S_LEN;
    const float SCL2 = 0.18033688011112042f;

    const int lrow = tid >> 3, lch = tid & 7;

    const uint32_t kAddrOff = (uint32_t)(((nc0 + (lane & 7)) * 72 + ((lane >> 3) * 8)) * 2);
    const uint32_t vAddrOff = (uint32_t)(((8 * (lane >> 4) + (lane & 7)) * 72
                                          + nc0 + 8 * ((lane >> 3) & 1)) * 2);

    int jlist[2] = { (int)blockIdx.x, 63 - (int)blockIdx.x };

    #pragma unroll 1
    for (int pb = 0; pb < 2; pb++) {
        const int j = jlist[pb];
        const size_t qrow = (size_t)b * S_LEN + 64 * j;

        // preload Q + tile 0
        {
            const __half* qp = g_qh + (qrow + lrow) * DHEAD + lch * 8;
            cp16(smb + QB + lrow * 144 + lch * 16, qp);
            const __half* kp = kg + (size_t)lrow * DHEAD + lch * 8;
            cp16(smb + K0B + lrow * 144 + lch * 16, kp);
            const __half* vp = vt + (size_t)lrow * S_LEN + lch * 8;
            cp16(smb + V0B + lrow * 144 + lch * 16, vp);
        }
        asm volatile("cp.async.commit_group;" ::: "memory");
        asm volatile("cp.async.wait_group 0;" ::: "memory");
        __syncthreads();

        uint32_t qf[4][4];
        #pragma unroll
        for (int s = 0; s < 4; s++) {
            const int k0 = 16 * s;
            qf[s][0] = *(const uint32_t*)&hs[(qr0 + g) * 72 + k0 + 2 * t4];
            qf[s][1] = *(const uint32_t*)&hs[(qr0 + g + 8) * 72 + k0 + 2 * t4];
            qf[s][2] = *(const uint32_t*)&hs[(qr0 + g) * 72 + k0 + 8 + 2 * t4];
            qf[s][3] = *(const uint32_t*)&hs[(qr0 + g + 8) * 72 + k0 + 8 + 2 * t4];
        }

        float oacc[8][4] = {};
        float l0 = 0.f, l1 = 0.f;

        for (int kb = 0; kb <= j; kb++) {
            if (kb > 0) {
                asm volatile("cp.async.wait_group 0;" ::: "memory");  // tile kb arrived
                __syncthreads();   // everyone finished reading tile kb-1
            }
            if (kb < j) {          // issue tile kb+1 into tile kb-1's buffer
                const int nK = (kb & 1) ? K0B : K1B;
                const int nV = (kb & 1) ? V0B : V1B;
                const __half* kp = kg + ((size_t)(kb + 1) * 64 + lrow) * DHEAD + lch * 8;
                cp16(smb + nK + lrow * 144 + lch * 16, kp);
                const __half* vp = vt + (size_t)lrow * S_LEN + (kb + 1) * 64 + lch * 8;
                cp16(smb + nV + lrow * 144 + lch * 16, vp);
                asm volatile("cp.async.commit_group;" ::: "memory");
            }

            const int kOffB = (kb & 1) ? K1B : K0B;
            const int vOffB = (kb & 1) ? V1B : V0B;

            // --- K fragments via ldmatrix.x4 ---
            uint32_t kf[2][8];
            {
                const uint32_t kb0 = smb + kOffB + kAddrOff;
                ldsm4(kf[0][0], kf[0][1], kf[0][2], kf[0][3], kb0);
                ldsm4(kf[0][4], kf[0][5], kf[0][6], kf[0][7], kb0 + 64);
                const uint32_t kb1 = kb0 + 8 * 144;
                ldsm4(kf[1][0], kf[1][1], kf[1][2], kf[1][3], kb1);
                ldsm4(kf[1][4], kf[1][5], kf[1][6], kf[1][7], kb1 + 64);
            }

            // --- S = Q K^T ---
            float sacc[2][4] = {};
            #pragma unroll
            for (int s = 0; s < 4; s++) {
                #pragma unroll
                for (int c = 0; c < 2; c++)
                    mma16(sacc[c], qf[s], &kf[c][2 * s]);
            }

            // --- softmax (no-rescale) -> fp16 P packed as A-frag ---
            const bool dg = (kb == j);
            const int ra = qr0 + g, rb = ra + 8;
            uint32_t pa[4];
            #pragma unroll
            for (int c = 0; c < 2; c++) {
                const int cb = nc0 + 8 * c + 2 * t4;
                float p00 = (!dg || cb     <= ra) ? ex2f(sacc[c][0] * SCL2) : 0.f;
                float p01 = (!dg || cb + 1 <= ra) ? ex2f(sacc[c][1] * SCL2) : 0.f;
                float p10 = (!dg || cb     <= rb) ? ex2f(sacc[c][2] * SCL2) : 0.f;
                float p11 = (!dg || cb + 1 <= rb) ? ex2f(sacc[c][3] * SCL2) : 0.f;
                pa[2 * c]     = h2pack(p00, p01);
                pa[2 * c + 1] = h2pack(p10, p11);
                float2 fa = h2unpack(pa[2 * c]);
                float2 fb = h2unpack(pa[2 * c + 1]);
                l0 += fa.x + fa.y;
                l1 += fb.x + fb.y;
            }

            // --- V fragments via ldmatrix.x4, then PV ---
            uint32_t vf[16];
            {
                const uint32_t vb0 = smb + vOffB + vAddrOff;
                ldsm4(vf[0],  vf[1],  vf[2],  vf[3],  vb0);
                ldsm4(vf[4],  vf[5],  vf[6],  vf[7],  vb0 + 16 * 144);
                ldsm4(vf[8],  vf[9],  vf[10], vf[11], vb0 + 32 * 144);
                ldsm4(vf[12], vf[13], vf[14], vf[15], vb0 + 48 * 144);
            }
            #pragma unroll
            for (int nt = 0; nt < 8; nt++)
                mma16(oacc[nt], pa, &vf[2 * nt]);
        }

        l0 += __shfl_xor_sync(0xffffffffu, l0, 1);
        l0 += __shfl_xor_sync(0xffffffffu, l0, 2);
        l1 += __shfl_xor_sync(0xffffffffu, l1, 1);
        l1 += __shfl_xor_sync(0xffffffffu, l1, 2);

        __syncthreads();   // all K/V reads done; RED may alias the buffers

        if (t4 == 0) {
            fL[w * 16 + g]     = l0;
            fL[w * 16 + g + 8] = l1;
        }
        {
            float* rw = fRED + w * (16 * 68);
            #pragma unroll
            for (int nt = 0; nt < 8; nt++) {
                const int cb = 8 * nt + 2 * t4;
                *(float2*)&rw[g * 68 + cb]       = make_float2(oacc[nt][0], oacc[nt][1]);
                *(float2*)&rw[(g + 8) * 68 + cb] = make_float2(oacc[nt][2], oacc[nt][3]);
            }
        }
        __syncthreads();

        {
            const int r  = tid >> 3;
            const int c0 = (tid & 7) * 8;
            const int wmr = r >> 4, ri = r & 15;
            float lt = 0.f;
            #pragma unroll
            for (int k = 0; k < 4; k++)
                lt += fL[(wmr + 4 * k) * 16 + ri];
            const float inv = 1.f / lt;

            float acc8[8] = {};
            #pragma unroll
            for (int k = 0; k < 4; k++) {
                const float* rp = fRED + (wmr + 4 * k) * (16 * 68) + ri * 68 + c0;
                #pragma unroll
                for (int e = 0; e < 8; e++) acc8[e] += rp[e];
            }
            __half* op = g_attnh + (qrow + r) * DHEAD + c0;
            #pragma unroll
            for (int e = 0; e < 8; e += 2)
                *(uint32_t*)&op[e] = h2pack(acc8[e] * inv, acc8[e + 1] * inv);
        }
        __syncthreads();   // RED/L reads done before next pair member reloads
    }
}

// ---------------------------------------------------------------------------
// Kernel 3: fp16 output projection, 2 row-tiles/CTA. grid = (64, 4), 256 thr.
// ---------------------------------------------------------------------------
#define PA0_B 0
#define PA1_B 18432
#define PB_B  36864
#define PROJ_SMEM 55296

__global__ void __launch_bounds__(256) proj_tc_kernel(
    const float* __restrict__ bo, float* __restrict__ out)
{
    extern __shared__ char smc[];
    __half* hs = (__half*)smc;
    const int tid = threadIdx.x;
    const int w = tid >> 5, lane = tid & 31, g = lane >> 2, t4 = lane & 3;
    const int wm = w & 3, wn = w >> 2;
    const int rowBase0 = blockIdx.x * 256;
    const int nBase    = blockIdx.y * 128;
    const uint32_t smb = smem_u32(smc);

    const int r = tid >> 1, h64 = tid & 1;

    {
        const __half* bp = g_wot + (size_t)(nBase + r) * DHEAD + h64 * 32;
        uint32_t ba = smb + PB_B + r * 144 + h64 * 64;
        #pragma unroll
        for (int i = 0; i < 4; i++) cp16(ba + 16 * i, bp + 8 * i);
        const __half* ap = g_attnh + (size_t)(rowBase0 + r) * DHEAD + h64 * 32;
        uint32_t aa = smb + PA0_B + r * 144 + h64 * 64;
        #pragma unroll
        for (int i = 0; i < 4; i++) cp16(aa + 16 * i, ap + 8 * i);
        asm volatile("cp.async.commit_group;" ::: "memory");
    }

    const __half* Bh = hs + PB_B / 2;

    #pragma unroll 1
    for (int t = 0; t < 2; t++) {
        __syncthreads();
        if (t < 1) {
            const __half* ap = g_attnh + (size_t)(rowBase0 + 128 + r) * DHEAD + h64 * 32;
            uint32_t aa = smb + PA1_B + r * 144 + h64 * 64;
            #pragma unroll
            for (int i = 0; i < 4; i++) cp16(aa + 16 * i, ap + 8 * i);
            asm volatile("cp.async.commit_group;" ::: "memory");
            asm volatile("cp.async.wait_group 1;" ::: "memory");
        } else {
            asm volatile("cp.async.wait_group 0;" ::: "memory");
        }
        __syncthreads();

        const __half* Ah = hs + ((t & 1) ? PA1_B : PA0_B) / 2;
        const int rowBase = rowBase0 + t * 128;

        float acc[2][8][4] = {};
        #pragma unroll
        for (int s = 0; s < 4; s++) {
            const int k0 = 16 * s;
            uint32_t af[2][4];
            #pragma unroll
            for (int i = 0; i < 2; i++) {
                const int m0 = 32 * wm + 16 * i;
                af[i][0] = *(const uint32_t*)&Ah[(m0 + g) * 72 + k0 + 2 * t4];
                af[i][1] = *(const uint32_t*)&Ah[(m0 + g + 8) * 72 + k0 + 2 * t4];
                af[i][2] = *(const uint32_t*)&Ah[(m0 + g) * 72 + k0 + 8 + 2 * t4];
                af[i][3] = *(const uint32_t*)&Ah[(m0 + g + 8) * 72 + k0 + 8 + 2 * t4];
            }
            #pragma unroll
            for (int nt = 0; nt < 8; nt++) {
                const int n0 = 64 * wn + 8 * nt;
                uint32_t bf[2];
                bf[0] = *(const uint32_t*)&Bh[(n0 + g) * 72 + k0 + 2 * t4];
                bf[1] = *(const uint32_t*)&Bh[(n0 + g) * 72 + k0 + 8 + 2 * t4];
                mma16(acc[0][nt], af[0], bf);
                mma16(acc[1][nt], af[1], bf);
            }
        }

        #pragma unroll
        for (int i = 0; i < 2; i++) {
            #pragma unroll
            for (int nt = 0; nt < 8; nt++) {
                const int col = nBase + 64 * wn + 8 * nt + 2 * t4;
                const float b0 = bo[col], b1 = bo[col + 1];
                const int rA = rowBase + 32 * wm + 16 * i + g;
                *(float2*)&out[(size_t)rA * D_MODEL + col] =
                    make_float2(acc[i][nt][0] + b0, acc[i][nt][1] + b1);
                *(float2*)&out[(size_t)(rA + 8) * D_MODEL + col] =
                    make_float2(acc[i][nt][2] + b0, acc[i][nt][3] + b1);
            }
        }
    }
}

// ---------------------------------------------------------------------------
extern "C" void kernel_launch(void* const* d_in, const int* in_sizes, int n_in,
                              void* d_out, int out_size)
{
    const float* x  = (const float*)d_in[0];
    const float* Wq = (const float*)d_in[1];
    const float* bq = (const float*)d_in[2];
    const float* Wk = (const float*)d_in[3];
    const float* bk = (const float*)d_in[4];
    const float* Wv = (const float*)d_in[5];
    const float* bv = (const float*)d_in[6];
    const float* Wo = (const float*)d_in[7];
    const float* bo = (const float*)d_in[8];
    float* out = (float*)d_out;

    cudaFuncSetAttribute(qkv_tc_kernel,
                         cudaFuncAttributeMaxDynamicSharedMemorySize, QKV_SMEM);
    cudaFuncSetAttribute(attn_mma_kernel,
                         cudaFuncAttributeMaxDynamicSharedMemorySize, ATTN_SMEM);
    cudaFuncSetAttribute(proj_tc_kernel,
                         cudaFuncAttributeMaxDynamicSharedMemorySize, PROJ_SMEM);

    preround_kernel<<<128, 256>>>(Wq, Wk, Wv, Wo);
    qkv_tc_kernel<<<BSROWS / 128, 256, QKV_SMEM>>>(x, bq, bk, bv);
    attn_mma_kernel<<<dim3(32, BATCH), 512, ATTN_SMEM>>>();
    proj_tc_kernel<<<dim3(64, D_MODEL / 128), 256, PROJ_SMEM>>>(bo, out);
}

// round 17
// speedup vs baseline: 1.0549x; 1.0151x over previous
#include <cuda_runtime.h>
#include <cuda_fp16.h>
#include <cstdint>

#define S_LEN   4096
#define BATCH   4
#define D_MODEL 512
#define DHEAD   64
#define BSROWS  (BATCH * S_LEN)

// Scratch (allocation-free rule: __device__ globals) — all fp16
__device__ __half g_qh[BSROWS * DHEAD];
__device__ __half g_kh[BSROWS * DHEAD];
__device__ __half g_vt[BATCH * DHEAD * S_LEN];   // V TRANSPOSED [b][dv][seq]
__device__ __half g_attnh[BSROWS * DHEAD];
__device__ __half g_wqt[DHEAD * D_MODEL];   // transposed [n=64][k=512]
__device__ __half g_wkt[DHEAD * D_MODEL];
__device__ __half g_wvt[DHEAD * D_MODEL];
__device__ __half g_wot[D_MODEL * DHEAD];   // transposed [n=512][k=64]

__device__ __forceinline__ float ex2f(float x) {
    float y; asm("ex2.approx.f32 %0, %1;" : "=f"(y) : "f"(x)); return y;
}
__device__ __forceinline__ uint32_t h2pack(float lo, float hi) {
    __half2 h = __floats2half2_rn(lo, hi);
    return *reinterpret_cast<uint32_t*>(&h);
}
__device__ __forceinline__ float2 h2unpack(uint32_t u) {
    __half2 h = *reinterpret_cast<__half2*>(&u);
    return __half22float2(h);
}
__device__ __forceinline__ uint32_t smem_u32(const void* p) {
    uint32_t a;
    asm("{ .reg .u64 t; cvta.to.shared.u64 t, %1; cvt.u32.u64 %0, t; }" : "=r"(a) : "l"(p));
    return a;
}
__device__ __forceinline__ void cp16(uint32_t s, const void* g) {
    asm volatile("cp.async.cg.shared.global [%0], [%1], 16;" :: "r"(s), "l"(g));
}
__device__ __forceinline__ void mma16(float* d, const uint32_t* a, const uint32_t* b) {
    asm volatile(
        "mma.sync.aligned.m16n8k16.row.col.f32.f16.f16.f32 "
        "{%0,%1,%2,%3}, {%4,%5,%6,%7}, {%8,%9}, {%0,%1,%2,%3};"
        : "+f"(d[0]), "+f"(d[1]), "+f"(d[2]), "+f"(d[3])
        : "r"(a[0]), "r"(a[1]), "r"(a[2]), "r"(a[3]), "r"(b[0]), "r"(b[1]));
}
__device__ __forceinline__ void ldsm4(uint32_t& r0, uint32_t& r1, uint32_t& r2,
                                      uint32_t& r3, uint32_t addr) {
    asm volatile("ldmatrix.sync.aligned.m8n8.x4.shared.b16 {%0,%1,%2,%3}, [%4];"
        : "=r"(r0), "=r"(r1), "=r"(r2), "=r"(r3) : "r"(addr));
}

// ---------------------------------------------------------------------------
// Kernel 0: weights only -> fp16 TRANSPOSED ([n][k]).
// ---------------------------------------------------------------------------
#define NWEL  (D_MODEL * DHEAD)

__global__ void __launch_bounds__(256) preround_kernel(
    const float* __restrict__ Wq, const float* __restrict__ Wk,
    const float* __restrict__ Wv, const float* __restrict__ Wo)
{
    const int total = 4 * NWEL;
    for (int r = blockIdx.x * blockDim.x + threadIdx.x; r < total;
         r += gridDim.x * blockDim.x) {
        int seg = r >> 15, o = r & (NWEL - 1);
        if (seg < 3) {
            const float* W = (seg == 0) ? Wq : (seg == 1) ? Wk : Wv;
            __half* wt = (seg == 0) ? g_wqt : (seg == 1) ? g_wkt : g_wvt;
            int k = o >> 6, n = o & 63;
            wt[n * D_MODEL + k] = __float2half_rn(W[o]);
        } else {
            int k = o >> 9, n = o & 511;
            g_wot[n * DHEAD + k] = __float2half_rn(Wo[o]);
        }
    }
}

// ---------------------------------------------------------------------------
// Kernel 1: MERGED fp16 QKV projection, fp32 X read directly; A and W
// fragments now via ldmatrix.x4 (16 ldsm4 per chunk instead of 64 LDS).
// grid = BSROWS/128, 256 thr. V stored transposed.
// ---------------------------------------------------------------------------
#define XB0 0
#define XB1 10240
#define WBASE 20480
#define WBUF_STRIDE 15360
#define WMODE_STRIDE 5120
#define QKV_SMEM 51200

__global__ void __launch_bounds__(256) qkv_tc_kernel(
    const float* __restrict__ x,
    const float* __restrict__ bq, const float* __restrict__ bk,
    const float* __restrict__ bv)
{
    extern __shared__ char smc[];

    const int tid = threadIdx.x;
    const int w = tid >> 5, lane = tid & 31, g = lane >> 2, t4 = lane & 3;
    const int wm = w & 3, wn = w >> 2;
    const int rowBase = blockIdx.x * 128;
    const uint32_t smb = smem_u32(smc);

    const int xr = tid >> 1, xc2 = tid & 1;
    const int wr = tid >> 2, wc2 = tid & 3;

    // per-lane ldmatrix byte offsets (row stride 80 B for both X and W tiles)
    const uint32_t aOff = (uint32_t)(((lane & 7) + 8 * ((lane >> 3) & 1)) * 80
                                     + (lane >> 4) * 16);
    const uint32_t bOff = (uint32_t)((lane & 7) * 80 + (lane >> 3) * 16);

    const float* xrow = x + (size_t)(rowBase + xr) * D_MODEL + xc2 * 16;

    float4 xv[4];
    #pragma unroll
    for (int i = 0; i < 4; i++) xv[i] = *(const float4*)(xrow + 4 * i);

    {
        const size_t woff = (size_t)wr * D_MODEL + wc2 * 8;
        uint32_t wa = smb + WBASE + wr * 80 + wc2 * 16;
        cp16(wa,                    g_wqt + woff);
        cp16(wa + WMODE_STRIDE,     g_wkt + woff);
        cp16(wa + 2 * WMODE_STRIDE, g_wvt + woff);
        asm volatile("cp.async.commit_group;" ::: "memory");
    }

    float accQ[2][4][4] = {}, accK[2][4][4] = {}, accV[2][4][4] = {};

    for (int kc = 0; kc < 16; kc++) {
        __syncthreads();

        {
            uint4 u0, u1;
            u0.x = h2pack(xv[0].x, xv[0].y); u0.y = h2pack(xv[0].z, xv[0].w);
            u0.z = h2pack(xv[1].x, xv[1].y); u0.w = h2pack(xv[1].z, xv[1].w);
            u1.x = h2pack(xv[2].x, xv[2].y); u1.y = h2pack(xv[2].z, xv[2].w);
            u1.z = h2pack(xv[3].x, xv[3].y); u1.w = h2pack(xv[3].z, xv[3].w);
            char* xb = smc + ((kc & 1) ? XB1 : XB0) + xr * 80 + xc2 * 32;
            *(uint4*)xb = u0;
            *(uint4*)(xb + 16) = u1;
        }

        if (kc < 15) {
            const float* xp = xrow + (kc + 1) * 32;
            #pragma unroll
            for (int i = 0; i < 4; i++) xv[i] = *(const float4*)(xp + 4 * i);
            const size_t woff = (size_t)wr * D_MODEL + (kc + 1) * 32 + wc2 * 8;
            uint32_t wa = smb + WBASE + ((kc + 1) & 1) * WBUF_STRIDE + wr * 80 + wc2 * 16;
            cp16(wa,                    g_wqt + woff);
            cp16(wa + WMODE_STRIDE,     g_wkt + woff);
            cp16(wa + 2 * WMODE_STRIDE, g_wvt + woff);
            asm volatile("cp.async.commit_group;" ::: "memory");
            asm volatile("cp.async.wait_group 1;" ::: "memory");
        } else {
            asm volatile("cp.async.wait_group 0;" ::: "memory");
        }
        __syncthreads();

        const uint32_t xbb = smb + ((kc & 1) ? XB1 : XB0);
        const uint32_t wbb = smb + WBASE + (kc & 1) * WBUF_STRIDE;

        // A fragments: 4 ldsm4 (2 m-halves x 2 k-steps)
        uint32_t af[2][2][4];
        #pragma unroll
        for (int i = 0; i < 2; i++) {
            const int m0 = 32 * wm + 16 * i;
            #pragma unroll
            for (int ks = 0; ks < 2; ks++)
                ldsm4(af[i][ks][0], af[i][ks][1], af[i][ks][2], af[i][ks][3],
                      xbb + aOff + (uint32_t)(m0 * 80 + ks * 32));
        }

        // B fragments per n-block: one ldsm4 per mode covers k0..31
        #pragma unroll
        for (int nt = 0; nt < 4; nt++) {
            const uint32_t nOff = bOff + (uint32_t)((32 * wn + 8 * nt) * 80);
            uint32_t bq4[4], bk4[4], bv4[4];
            ldsm4(bq4[0], bq4[1], bq4[2], bq4[3], wbb + nOff);
            ldsm4(bk4[0], bk4[1], bk4[2], bk4[3], wbb + WMODE_STRIDE + nOff);
            ldsm4(bv4[0], bv4[1], bv4[2], bv4[3], wbb + 2 * WMODE_STRIDE + nOff);
            #pragma unroll
            for (int ks = 0; ks < 2; ks++) {
                mma16(accQ[0][nt], af[0][ks], &bq4[2 * ks]);
                mma16(accQ[1][nt], af[1][ks], &bq4[2 * ks]);
                mma16(accK[0][nt], af[0][ks], &bk4[2 * ks]);
                mma16(accK[1][nt], af[1][ks], &bk4[2 * ks]);
                mma16(accV[0][nt], af[0][ks], &bv4[2 * ks]);
                mma16(accV[1][nt], af[1][ks], &bv4[2 * ks]);
            }
        }
    }

    #pragma unroll
    for (int i = 0; i < 2; i++) {
        #pragma unroll
        for (int nt = 0; nt < 4; nt++) {
            const int col = 32 * wn + 8 * nt + 2 * t4;
            const int rA = rowBase + 32 * wm + 16 * i + g;
            {
                const float b0 = bq[col], b1 = bq[col + 1];
                *(uint32_t*)&g_qh[(size_t)rA * DHEAD + col] =
                    h2pack(accQ[i][nt][0] + b0, accQ[i][nt][1] + b1);
                *(uint32_t*)&g_qh[(size_t)(rA + 8) * DHEAD + col] =
                    h2pack(accQ[i][nt][2] + b0, accQ[i][nt][3] + b1);
            }
            {
                const float b0 = bk[col], b1 = bk[col + 1];
                *(uint32_t*)&g_kh[(size_t)rA * DHEAD + col] =
                    h2pack(accK[i][nt][0] + b0, accK[i][nt][1] + b1);
                *(uint32_t*)&g_kh[(size_t)(rA + 8) * DHEAD + col] =
                    h2pack(accK[i][nt][2] + b0, accK[i][nt][3] + b1);
            }
            {
                const float b0 = bv[col], b1 = bv[col + 1];
                const int bb = rA >> 12, s0 = rA & (S_LEN - 1);
                __half* vt = g_vt + (size_t)bb * DHEAD * S_LEN;
                vt[(size_t)col * S_LEN + s0]           = __float2half_rn(accV[i][nt][0] + b0);
                vt[(size_t)(col + 1) * S_LEN + s0]     = __float2half_rn(accV[i][nt][1] + b1);
                vt[(size_t)col * S_LEN + s0 + 8]       = __float2half_rn(accV[i][nt][2] + b0);
                vt[(size_t)(col + 1) * S_LEN + s0 + 8] = __float2half_rn(accV[i][nt][3] + b1);
            }
        }
    }
}

// attention smem (bytes): Q | K0 V0 K1 V1 (each 9216) | RED fp32 (aliases)
#define QB   0
#define K0B  9216
#define V0B  18432
#define K1B  27648
#define V1B  36864
#define REDB 9216
#define LB   78848
#define ATTN_SMEM 79872

// ---------------------------------------------------------------------------
// Kernel 2: fp16 causal flash attention — EXACT R14 structure (two barriers,
// prefetch issued before wait_group 1), ldmatrix K/V fragments.
// ---------------------------------------------------------------------------
__global__ void __launch_bounds__(512, 1) attn_mma_kernel()
{
    extern __shared__ char smc[];
    __half* hs = (__half*)smc;
    float* fRED = (float*)(smc + REDB);
    float* fL   = (float*)(smc + LB);

    const int tid  = threadIdx.x;
    const int w    = tid >> 5, lane = tid & 31;
    const int g    = lane >> 2, t4 = lane & 3;
    const int b    = blockIdx.y;
    const int wm   = w & 3, wk = w >> 2;
    const int qr0  = 16 * wm;
    const int nc0  = 16 * wk;
    const uint32_t smb = smem_u32(smc);

    const __half* kg = g_kh + (size_t)b * S_LEN * DHEAD;
    const __half* vt = g_vt + (size_t)b * DHEAD * S_LEN;
    const float SCL2 = 0.18033688011112042f;

    const int lrow = tid >> 3, lch = tid & 7;

    const uint32_t kAddrOff = (uint32_t)(((nc0 + (lane & 7)) * 72 + ((lane >> 3) * 8)) * 2);
    const uint32_t vAddrOff = (uint32_t)(((8 * (lane >> 4) + (lane & 7)) * 72
                                          + nc0 + 8 * ((lane >> 3) & 1)) * 2);

    int jlist[2] = { (int)blockIdx.x, 63 - (int)blockIdx.x };

    #pragma unroll 1
    for (int pb = 0; pb < 2; pb++) {
        const int j = jlist[pb];
        const size_t qrow = (size_t)b * S_LEN + 64 * j;

        {
            const __half* qp = g_qh + (qrow + lrow) * DHEAD + lch * 8;
            cp16(smb + QB + lrow * 144 + lch * 16, qp);
            const __half* kp = kg + (size_t)lrow * DHEAD + lch * 8;
            cp16(smb + K0B + lrow * 144 + lch * 16, kp);
            const __half* vp = vt + (size_t)lrow * S_LEN + lch * 8;
            cp16(smb + V0B + lrow * 144 + lch * 16, vp);
        }
        asm volatile("cp.async.commit_group;" ::: "memory");
        asm volatile("cp.async.wait_group 0;" ::: "memory");
        __syncthreads();

        uint32_t qf[4][4];
        #pragma unroll
        for (int s = 0; s < 4; s++) {
            const int k0 = 16 * s;
            qf[s][0] = *(const uint32_t*)&hs[(qr0 + g) * 72 + k0 + 2 * t4];
            qf[s][1] = *(const uint32_t*)&hs[(qr0 + g + 8) * 72 + k0 + 2 * t4];
            qf[s][2] = *(const uint32_t*)&hs[(qr0 + g) * 72 + k0 + 8 + 2 * t4];
            qf[s][3] = *(const uint32_t*)&hs[(qr0 + g + 8) * 72 + k0 + 8 + 2 * t4];
        }

        float oacc[8][4] = {};
        float l0 = 0.f, l1 = 0.f;

        for (int kb = 0; kb <= j; kb++) {
            const int kOffB = (kb & 1) ? K1B : K0B;
            const int vOffB = (kb & 1) ? V1B : V0B;

            __syncthreads();

            if (kb < j) {
                const int nK = (kb & 1) ? K0B : K1B;
                const int nV = (kb & 1) ? V0B : V1B;
                const __half* kp = kg + ((size_t)(kb + 1) * 64 + lrow) * DHEAD + lch * 8;
                cp16(smb + nK + lrow * 144 + lch * 16, kp);
                const __half* vp = vt + (size_t)lrow * S_LEN + (kb + 1) * 64 + lch * 8;
                cp16(smb + nV + lrow * 144 + lch * 16, vp);
                asm volatile("cp.async.commit_group;" ::: "memory");
                asm volatile("cp.async.wait_group 1;" ::: "memory");
            } else {
                asm volatile("cp.async.wait_group 0;" ::: "memory");
            }
            __syncthreads();

            // --- K fragments via ldmatrix.x4 ---
            uint32_t kf[2][8];
            {
                const uint32_t kb0 = smb + kOffB + kAddrOff;
                ldsm4(kf[0][0], kf[0][1], kf[0][2], kf[0][3], kb0);
                ldsm4(kf[0][4], kf[0][5], kf[0][6], kf[0][7], kb0 + 64);
                const uint32_t kb1 = kb0 + 8 * 144;
                ldsm4(kf[1][0], kf[1][1], kf[1][2], kf[1][3], kb1);
                ldsm4(kf[1][4], kf[1][5], kf[1][6], kf[1][7], kb1 + 64);
            }

            // --- S = Q K^T ---
            float sacc[2][4] = {};
            #pragma unroll
            for (int s = 0; s < 4; s++) {
                #pragma unroll
                for (int c = 0; c < 2; c++)
                    mma16(sacc[c], qf[s], &kf[c][2 * s]);
            }

            // --- softmax (no-rescale) -> fp16 P packed as A-frag ---
            const bool dg = (kb == j);
            const int ra = qr0 + g, rb = ra + 8;
            uint32_t pa[4];
            #pragma unroll
            for (int c = 0; c < 2; c++) {
                const int cb = nc0 + 8 * c + 2 * t4;
                float p00 = (!dg || cb     <= ra) ? ex2f(sacc[c][0] * SCL2) : 0.f;
                float p01 = (!dg || cb + 1 <= ra) ? ex2f(sacc[c][1] * SCL2) : 0.f;
                float p10 = (!dg || cb     <= rb) ? ex2f(sacc[c][2] * SCL2) : 0.f;
                float p11 = (!dg || cb + 1 <= rb) ? ex2f(sacc[c][3] * SCL2) : 0.f;
                pa[2 * c]     = h2pack(p00, p01);
                pa[2 * c + 1] = h2pack(p10, p11);
                float2 fa = h2unpack(pa[2 * c]);
                float2 fb = h2unpack(pa[2 * c + 1]);
                l0 += fa.x + fa.y;
                l1 += fb.x + fb.y;
            }

            // --- V fragments via ldmatrix.x4, then PV ---
            uint32_t vf[16];
            {
                const uint32_t vb0 = smb + vOffB + vAddrOff;
                ldsm4(vf[0],  vf[1],  vf[2],  vf[3],  vb0);
                ldsm4(vf[4],  vf[5],  vf[6],  vf[7],  vb0 + 16 * 144);
                ldsm4(vf[8],  vf[9],  vf[10], vf[11], vb0 + 32 * 144);
                ldsm4(vf[12], vf[13], vf[14], vf[15], vb0 + 48 * 144);
            }
            #pragma unroll
            for (int nt = 0; nt < 8; nt++)
                mma16(oacc[nt], pa, &vf[2 * nt]);
        }

        l0 += __shfl_xor_sync(0xffffffffu, l0, 1);
        l0 += __shfl_xor_sync(0xffffffffu, l0, 2);
        l1 += __shfl_xor_sync(0xffffffffu, l1, 1);
        l1 += __shfl_xor_sync(0xffffffffu, l1, 2);

        __syncthreads();   // all K/V reads done; RED may alias the buffers

        if (t4 == 0) {
            fL[w * 16 + g]     = l0;
            fL[w * 16 + g + 8] = l1;
        }
        {
            float* rw = fRED + w * (16 * 68);
            #pragma unroll
            for (int nt = 0; nt < 8; nt++) {
                const int cb = 8 * nt + 2 * t4;
                *(float2*)&rw[g * 68 + cb]       = make_float2(oacc[nt][0], oacc[nt][1]);
                *(float2*)&rw[(g + 8) * 68 + cb] = make_float2(oacc[nt][2], oacc[nt][3]);
            }
        }
        __syncthreads();

        {
            const int r  = tid >> 3;
            const int c0 = (tid & 7) * 8;
            const int wmr = r >> 4, ri = r & 15;
            float lt = 0.f;
            #pragma unroll
            for (int k = 0; k < 4; k++)
                lt += fL[(wmr + 4 * k) * 16 + ri];
            const float inv = 1.f / lt;

            float acc8[8] = {};
            #pragma unroll
            for (int k = 0; k < 4; k++) {
                const float* rp = fRED + (wmr + 4 * k) * (16 * 68) + ri * 68 + c0;
                #pragma unroll
                for (int e = 0; e < 8; e++) acc8[e] += rp[e];
            }
            __half* op = g_attnh + (qrow + r) * DHEAD + c0;
            #pragma unroll
            for (int e = 0; e < 8; e += 2)
                *(uint32_t*)&op[e] = h2pack(acc8[e] * inv, acc8[e + 1] * inv);
        }
        __syncthreads();   // RED/L reads done before next pair member reloads
    }
}

// ---------------------------------------------------------------------------
// Kernel 3: fp16 output projection, 2 row-tiles/CTA. grid = (64, 4), 256 thr.
// ---------------------------------------------------------------------------
#define PA0_B 0
#define PA1_B 18432
#define PB_B  36864
#define PROJ_SMEM 55296

__global__ void __launch_bounds__(256) proj_tc_kernel(
    const float* __restrict__ bo, float* __restrict__ out)
{
    extern __shared__ char smc[];
    __half* hs = (__half*)smc;
    const int tid = threadIdx.x;
    const int w = tid >> 5, lane = tid & 31, g = lane >> 2, t4 = lane & 3;
    const int wm = w & 3, wn = w >> 2;
    const int rowBase0 = blockIdx.x * 256;
    const int nBase    = blockIdx.y * 128;
    const uint32_t smb = smem_u32(smc);

    const int r = tid >> 1, h64 = tid & 1;

    {
        const __half* bp = g_wot + (size_t)(nBase + r) * DHEAD + h64 * 32;
        uint32_t ba = smb + PB_B + r * 144 + h64 * 64;
        #pragma unroll
        for (int i = 0; i < 4; i++) cp16(ba + 16 * i, bp + 8 * i);
        const __half* ap = g_attnh + (size_t)(rowBase0 + r) * DHEAD + h64 * 32;
        uint32_t aa = smb + PA0_B + r * 144 + h64 * 64;
        #pragma unroll
        for (int i = 0; i < 4; i++) cp16(aa + 16 * i, ap + 8 * i);
        asm volatile("cp.async.commit_group;" ::: "memory");
    }

    const __half* Bh = hs + PB_B / 2;

    #pragma unroll 1
    for (int t = 0; t < 2; t++) {
        __syncthreads();
        if (t < 1) {
            const __half* ap = g_attnh + (size_t)(rowBase0 + 128 + r) * DHEAD + h64 * 32;
            uint32_t aa = smb + PA1_B + r * 144 + h64 * 64;
            #pragma unroll
            for (int i = 0; i < 4; i++) cp16(aa + 16 * i, ap + 8 * i);
            asm volatile("cp.async.commit_group;" ::: "memory");
            asm volatile("cp.async.wait_group 1;" ::: "memory");
        } else {
            asm volatile("cp.async.wait_group 0;" ::: "memory");
        }
        __syncthreads();

        const __half* Ah = hs + ((t & 1) ? PA1_B : PA0_B) / 2;
        const int rowBase = rowBase0 + t * 128;

        float acc[2][8][4] = {};
        #pragma unroll
        for (int s = 0; s < 4; s++) {
            const int k0 = 16 * s;
            uint32_t af[2][4];
            #pragma unroll
            for (int i = 0; i < 2; i++) {
                const int m0 = 32 * wm + 16 * i;
                af[i][0] = *(const uint32_t*)&Ah[(m0 + g) * 72 + k0 + 2 * t4];
                af[i][1] = *(const uint32_t*)&Ah[(m0 + g + 8) * 72 + k0 + 2 * t4];
                af[i][2] = *(const uint32_t*)&Ah[(m0 + g) * 72 + k0 + 8 + 2 * t4];
                af[i][3] = *(const uint32_t*)&Ah[(m0 + g + 8) * 72 + k0 + 8 + 2 * t4];
            }
            #pragma unroll
            for (int nt = 0; nt < 8; nt++) {
                const int n0 = 64 * wn + 8 * nt;
                uint32_t bf[2];
                bf[0] = *(const uint32_t*)&Bh[(n0 + g) * 72 + k0 + 2 * t4];
                bf[1] = *(const uint32_t*)&Bh[(n0 + g) * 72 + k0 + 8 + 2 * t4];
                mma16(acc[0][nt], af[0], bf);
                mma16(acc[1][nt], af[1], bf);
            }
        }

        #pragma unroll
        for (int i = 0; i < 2; i++) {
            #pragma unroll
            for (int nt = 0; nt < 8; nt++) {
                const int col = nBase + 64 * wn + 8 * nt + 2 * t4;
                const float b0 = bo[col], b1 = bo[col + 1];
                const int rA = rowBase + 32 * wm + 16 * i + g;
                *(float2*)&out[(size_t)rA * D_MODEL + col] =
                    make_float2(acc[i][nt][0] + b0, acc[i][nt][1] + b1);
                *(float2*)&out[(size_t)(rA + 8) * D_MODEL + col] =
                    make_float2(acc[i][nt][2] + b0, acc[i][nt][3] + b1);
            }
        }
    }
}

// ---------------------------------------------------------------------------
extern "C" void kernel_launch(void* const* d_in, const int* in_sizes, int n_in,
                              void* d_out, int out_size)
{
    const float* x  = (const float*)d_in[0];
    const float* Wq = (const float*)d_in[1];
    const float* bq = (const float*)d_in[2];
    const float* Wk = (const float*)d_in[3];
    const float* bk = (const float*)d_in[4];
    const float* Wv = (const float*)d_in[5];
    const float* bv = (const float*)d_in[6];
    const float* Wo = (const float*)d_in[7];
    const float* bo = (const float*)d_in[8];
    float* out = (float*)d_out;

    cudaFuncSetAttribute(qkv_tc_kernel,
                         cudaFuncAttributeMaxDynamicSharedMemorySize, QKV_SMEM);
    cudaFuncSetAttribute(attn_mma_kernel,
                         cudaFuncAttributeMaxDynamicSharedMemorySize, ATTN_SMEM);
    cudaFuncSetAttribute(proj_tc_kernel,
                         cudaFuncAttributeMaxDynamicSharedMemorySize, PROJ_SMEM);

    preround_kernel<<<128, 256>>>(Wq, Wk, Wv, Wo);
    qkv_tc_kernel<<<BSROWS / 128, 256, QKV_SMEM>>>(x, bq, bk, bv);
    attn_mma_kernel<<<dim3(32, BATCH), 512, ATTN_SMEM>>>();
    proj_tc_kernel<<<dim3(64, D_MODEL / 128), 256, PROJ_SMEM>>>(bo, out);
}